// round 10
// baseline (speedup 1.0000x reference)
#include <cuda_runtime.h>

// GCN 2-layer, GB300 — round 10: scatter contention fix + bigger tiles.
// R9 won (239.7us) with smem-staged partition. Budget: scatter ~90, passes
// ~55-60 each, deg 17. R10: (a) 2x replicated rank counters (halve smem
// same-address ATOMS contention), (b) 4096-edge tiles (halve fixed costs,
// double write-run length), (c) zeroing split into 4 kernels so k_scatter
// is the 6th launch and finally gets profiled.

#define NN     200000
#define NE     12800000
#define BSHIFT 11
#define BINW   2048
#define NBINS  98                    // ceil(NN / BINW)
#define NPAD   (NBINS * BINW)        // 200704
#define TILE   4096
#define NTILES (NE / TILE)           // 3125
#define CAPB   140000                // per-bin capacity (mean 131k, sigma ~360)
#define NCHUNK 8

__device__ unsigned d_edges[NBINS * CAPB];  // packed (localdst<<18)|src
__device__ int      d_cur[NBINS];           // per-bin write cursors
__device__ int      d_cnt[NPAD];
__device__ float2   d_u  [NPAD];
__device__ float    d_dinv[NN];
__device__ float2   d_g  [NN];
__device__ float2   d_h2 [NN];

// ---------------- init (5 cheap kernels -> k_scatter is launch #6) --------

__global__ void k_zero_cur() {
    int i = threadIdx.x;
    if (i < NBINS) d_cur[i] = 0;
}

__global__ void k_zero_acc(int base) {
    int i = base + blockIdx.x * blockDim.x + threadIdx.x;
    if (i < NPAD) { d_cnt[i] = 0; d_u[i] = make_float2(0.f, 0.f); }
}

// ---------------- partition: tile-staged, replicated rank counters --------

__global__ void k_scatter(const int4* __restrict__ src4,
                          const int4* __restrict__ dst4) {
    __shared__ unsigned stage[TILE];            // 16 KB
    __shared__ int cnt[2][NBINS];               // replicated rank counters
    __shared__ int segoff[NBINS];
    __shared__ int base1[NBINS];
    __shared__ int gbase[NBINS];
    __shared__ int total[NBINS];
    int tid = threadIdx.x;
    int rep = (tid >> 5) & 1;                   // warps alternate replicas
    for (int i = tid; i < 2 * NBINS; i += 256) ((int*)cnt)[i] = 0;
    int b4 = blockIdx.x * (TILE / 4);
    int ss[16], dd[16];
#pragma unroll
    for (int q = 0; q < 4; q++) {
        int4 s = __ldcs(&src4[b4 + q * 256 + tid]);
        int4 d = __ldcs(&dst4[b4 + q * 256 + tid]);
        ss[4*q] = s.x; ss[4*q+1] = s.y; ss[4*q+2] = s.z; ss[4*q+3] = s.w;
        dd[4*q] = d.x; dd[4*q+1] = d.y; dd[4*q+2] = d.z; dd[4*q+3] = d.w;
    }
    __syncthreads();
    unsigned wd[16]; int bn[16], rk[16];
#pragma unroll
    for (int r = 0; r < 16; r++) {
        bn[r] = dd[r] >> BSHIFT;
        wd[r] = ((unsigned)(dd[r] & (BINW - 1)) << 18) | (unsigned)ss[r];
        rk[r] = atomicAdd(&cnt[rep][bn[r]], 1);
    }
    __syncthreads();
    if (tid == 0) {                             // 98-entry serial scan
        int run = 0;
#pragma unroll 1
        for (int b = 0; b < NBINS; b++) {
            int c0 = cnt[0][b], c1 = cnt[1][b];
            segoff[b] = run;
            base1[b]  = run + c0;
            total[b]  = c0 + c1;
            run += c0 + c1;
        }
    }
    __syncthreads();
    if (tid < NBINS) gbase[tid] = atomicAdd(&d_cur[tid], total[tid]);
#pragma unroll
    for (int r = 0; r < 16; r++) {
        int p = (rep ? base1[bn[r]] : segoff[bn[r]]) + rk[r];
        stage[p] = wd[r];
    }
    __syncthreads();
    for (int i = tid; i < TILE; i += 256) {
        int lo = 0, hi = NBINS;                 // segment containing i
        while (lo + 1 < hi) {
            int mid = (lo + hi) >> 1;
            if (segoff[mid] <= i) lo = mid; else hi = mid;
        }
        int pos = gbase[lo] + (i - segoff[lo]);
        if (pos < CAPB)                         // never triggers; OOB guard
            d_edges[lo * CAPB + pos] = stage[i];
    }
}

// ---------------- binned degree ----------------

__global__ void k_deg() {
    __shared__ int acc[BINW];
    int tid = threadIdx.x;
    int bin = blockIdx.x / NCHUNK, ch = blockIdx.x % NCHUNK;
    for (int i = tid; i < BINW; i += 256) acc[i] = 0;
    __syncthreads();
    int cnt  = d_cur[bin];
    int base = bin * CAPB;
    int lo = base + (int)((long long)cnt * ch / NCHUNK);
    int hi = base + (int)((long long)cnt * (ch + 1) / NCHUNK);
    for (int e = lo + tid; e < hi; e += 256)
        atomicAdd(&acc[__ldcs(&d_edges[e]) >> 18], 1);
    __syncthreads();
    for (int ld = tid; ld < BINW; ld += 256) {
        int v = acc[ld];
        if (v)
            asm volatile("red.global.add.u32 [%0], %1;"
                         :: "l"(&d_cnt[(bin << BSHIFT) + ld]), "r"(v) : "memory");
    }
}

// ---------------- dense node kernels ----------------

__global__ void k_nodeA(const float2* __restrict__ x) {
    int i = blockIdx.x * blockDim.x + threadIdx.x;
    if (i >= NN) return;
    float deg  = (float)d_cnt[i] + 1.0f;        // +1 self-loop
    float dinv = rsqrtf(deg);
    d_dinv[i] = dinv;
    float2 xv = x[i];
    d_g[i] = make_float2(xv.x * dinv, xv.y * dinv);
}

__global__ void k_nodeB(const float2* __restrict__ x,
                        const float*  __restrict__ W1,   // [2,16]
                        const float*  __restrict__ b1,   // [16]
                        const float*  __restrict__ W2) { // [16,2]
    int i = blockIdx.x * blockDim.x + threadIdx.x;
    if (i >= NN) return;
    float dinv = d_dinv[i];
    float idg  = dinv * dinv;
    float2 xv  = __ldg(&x[i]);
    float2 u   = d_u[i];
    float ax = fmaf(u.x, dinv, xv.x * idg);
    float ay = fmaf(u.y, dinv, xv.y * idg);
    float h20 = 0.f, h21 = 0.f;
#pragma unroll
    for (int f = 0; f < 16; f++) {
        float a = fmaf(ax, __ldg(&W1[f]), fmaf(ay, __ldg(&W1[16 + f]), __ldg(&b1[f])));
        a = fmaxf(a, 0.f);
        h20 = fmaf(a, __ldg(&W2[2 * f]),     h20);
        h21 = fmaf(a, __ldg(&W2[2 * f + 1]), h21);
    }
    d_h2[i] = make_float2(h20, h21);
    d_g[i]  = make_float2(h20 * dinv, h21 * dinv);
    d_u[i]  = make_float2(0.f, 0.f);            // re-zero for pass 2
}

__global__ void k_nodeC(const float* __restrict__ b2, float2* __restrict__ out) {
    int i = blockIdx.x * blockDim.x + threadIdx.x;
    if (i >= NN) return;
    float dinv = d_dinv[i];
    float idg  = dinv * dinv;
    float2 u  = d_u[i];
    float2 h2 = d_h2[i];
    out[i] = make_float2(fmaf(u.x, dinv, fmaf(h2.x, idg, __ldg(&b2[0]))),
                         fmaf(u.y, dinv, fmaf(h2.y, idg, __ldg(&b2[1]))));
}

// ---------------- binned gather + smem-accumulate pass ----------------

__global__ void k_pass() {
    __shared__ float accx[BINW];
    __shared__ float accy[BINW];
    int tid = threadIdx.x;
    int bin = blockIdx.x / NCHUNK, ch = blockIdx.x % NCHUNK;
    for (int i = tid; i < BINW; i += 256) { accx[i] = 0.f; accy[i] = 0.f; }
    __syncthreads();
    int cnt  = d_cur[bin];
    int base = bin * CAPB;
    int lo = base + (int)((long long)cnt * ch / NCHUNK);
    int hi = base + (int)((long long)cnt * (ch + 1) / NCHUNK);
    int e = lo + tid;
    for (; e + 3 * 256 < hi; e += 4 * 256) {
        unsigned w0 = __ldcs(&d_edges[e]);
        unsigned w1 = __ldcs(&d_edges[e + 256]);
        unsigned w2 = __ldcs(&d_edges[e + 512]);
        unsigned w3 = __ldcs(&d_edges[e + 768]);
        float2 g0 = __ldg(&d_g[w0 & 0x3FFFFu]);
        float2 g1 = __ldg(&d_g[w1 & 0x3FFFFu]);
        float2 g2 = __ldg(&d_g[w2 & 0x3FFFFu]);
        float2 g3 = __ldg(&d_g[w3 & 0x3FFFFu]);
        atomicAdd(&accx[w0 >> 18], g0.x); atomicAdd(&accy[w0 >> 18], g0.y);
        atomicAdd(&accx[w1 >> 18], g1.x); atomicAdd(&accy[w1 >> 18], g1.y);
        atomicAdd(&accx[w2 >> 18], g2.x); atomicAdd(&accy[w2 >> 18], g2.y);
        atomicAdd(&accx[w3 >> 18], g3.x); atomicAdd(&accy[w3 >> 18], g3.y);
    }
    for (; e < hi; e += 256) {
        unsigned w = __ldcs(&d_edges[e]);
        float2 g = __ldg(&d_g[w & 0x3FFFFu]);
        atomicAdd(&accx[w >> 18], g.x);
        atomicAdd(&accy[w >> 18], g.y);
    }
    __syncthreads();
    for (int ld = tid; ld < BINW; ld += 256) {
        float vx = accx[ld], vy = accy[ld];
        if (vx != 0.f || vy != 0.f)
            asm volatile("red.global.add.v2.f32 [%0], {%1, %2};"
                         :: "l"(&d_u[(bin << BSHIFT) + ld]), "f"(vx), "f"(vy) : "memory");
    }
}

// ---------------- launch ----------------

extern "C" void kernel_launch(void* const* d_in, const int* in_sizes, int n_in,
                              void* d_out, int out_size) {
    // metadata order: x, W1, b1, W2, b2, edge_index
    const float2* x  = (const float2*)d_in[0];
    const float*  W1 = (const float*) d_in[1];
    const float*  b1 = (const float*) d_in[2];
    const float*  W2 = (const float*) d_in[3];
    const float*  b2 = (const float*) d_in[4];
    const int*    ei = (const int*)   d_in[5];     // [2, NE] row-major
    const int4*   src4 = (const int4*)(ei);
    const int4*   dst4 = (const int4*)(ei + NE);
    float2* out = (float2*)d_out;

    const int NT = 256;
    const int nodeBlocks = (NN + NT - 1) / NT;
    const int QUART = (NPAD + 3) / 4;
    const int qBlocks = (QUART + NT - 1) / NT;
    const int dpBlocks = NBINS * NCHUNK;            // 784

    k_zero_cur<<<1,          128>>>();
    k_zero_acc<<<qBlocks,    NT>>>(0);              // launches 2..5
    k_zero_acc<<<qBlocks,    NT>>>(QUART);
    k_zero_acc<<<qBlocks,    NT>>>(2 * QUART);
    k_zero_acc<<<qBlocks,    NT>>>(3 * QUART);
    k_scatter <<<NTILES,     NT>>>(src4, dst4);     // 6th -> ncu capture
    k_deg     <<<dpBlocks,   NT>>>();
    k_nodeA   <<<nodeBlocks, NT>>>(x);
    k_pass    <<<dpBlocks,   NT>>>();
    k_nodeB   <<<nodeBlocks, NT>>>(x, W1, b1, W2);
    k_pass    <<<dpBlocks,   NT>>>();
    k_nodeC   <<<nodeBlocks, NT>>>(b2, out);
}

// round 11
// speedup vs baseline: 1.1459x; 1.1459x over previous
#include <cuda_runtime.h>

// GCN 2-layer, GB300 — round 11: R9 base (239.7us) + two scatter fixes.
// R10 regressed from register spill (16-elem arrays @ TILE=4096), not from
// counter replication; reverting tile size, keeping replication. Also kill
// the staged-writer binary search (~90M smem loads) via a binof[] byte map.
// Launch order puts k_scatter 4th = the slot ncu actually captures.

#define NN     200000
#define NE     12800000
#define BSHIFT 11
#define BINW   2048
#define NBINS  98                    // ceil(NN / BINW)
#define NPAD   (NBINS * BINW)        // 200704
#define TILE   2048
#define NTILES (NE / TILE)           // 6250
#define CAPB   140000                // per-bin capacity (mean ~131k)
#define NCHUNK 8

__device__ unsigned d_edges[NBINS * CAPB];  // packed (localdst<<18)|src
__device__ int      d_cur[NBINS];           // per-bin write cursors
__device__ int      d_cnt[NPAD];
__device__ float2   d_u  [NPAD];
__device__ float    d_dinv[NN];
__device__ float2   d_g  [NN];
__device__ float2   d_h2 [NN];

// ---------------- init ----------------

__global__ void k_zero_cur() {
    int i = threadIdx.x;
    if (i < NBINS) d_cur[i] = 0;
}

__global__ void k_zero_acc(int base) {
    int i = base + blockIdx.x * blockDim.x + threadIdx.x;
    if (i < NPAD) { d_cnt[i] = 0; d_u[i] = make_float2(0.f, 0.f); }
}

// ---------------- partition: tile-staged, coalesced writes ----------------

__global__ void k_scatter(const int4* __restrict__ src4,
                          const int4* __restrict__ dst4) {
    __shared__ unsigned stage[TILE];             // 8 KB
    __shared__ unsigned char binof[TILE];        // 2 KB: bin of each staged slot
    __shared__ int cnt[2][NBINS];                // replicated rank counters
    __shared__ int segoff[NBINS];
    __shared__ int base1[NBINS];
    __shared__ int gbase[NBINS];
    __shared__ int total[NBINS];
    int tid = threadIdx.x;
    int rep = (tid >> 5) & 1;                    // warps alternate replicas
    for (int i = tid; i < 2 * NBINS; i += 256) ((int*)cnt)[i] = 0;
    int b4 = blockIdx.x * (TILE / 4);
    int4 sa = __ldcs(&src4[b4 + tid]);
    int4 sb = __ldcs(&src4[b4 + 256 + tid]);
    int4 da = __ldcs(&dst4[b4 + tid]);
    int4 db = __ldcs(&dst4[b4 + 256 + tid]);
    int ss[8] = {sa.x, sa.y, sa.z, sa.w, sb.x, sb.y, sb.z, sb.w};
    int dd[8] = {da.x, da.y, da.z, da.w, db.x, db.y, db.z, db.w};
    __syncthreads();
    unsigned wd[8]; int bn[8], rk[8];
#pragma unroll
    for (int r = 0; r < 8; r++) {
        bn[r] = dd[r] >> BSHIFT;
        wd[r] = ((unsigned)(dd[r] & (BINW - 1)) << 18) | (unsigned)ss[r];
        rk[r] = atomicAdd(&cnt[rep][bn[r]], 1);
    }
    __syncthreads();
    if (tid == 0) {                              // 98-entry serial scan
        int run = 0;
#pragma unroll 1
        for (int b = 0; b < NBINS; b++) {
            int c0 = cnt[0][b], c1 = cnt[1][b];
            segoff[b] = run;
            base1[b]  = run + c0;
            total[b]  = c0 + c1;
            run += c0 + c1;
        }
    }
    __syncthreads();
    if (tid < NBINS) gbase[tid] = atomicAdd(&d_cur[tid], total[tid]);
#pragma unroll
    for (int r = 0; r < 8; r++) {
        int p = (rep ? base1[bn[r]] : segoff[bn[r]]) + rk[r];
        stage[p] = wd[r];
        binof[p] = (unsigned char)bn[r];
    }
    __syncthreads();
    for (int i = tid; i < TILE; i += 256) {      // direct map, no search
        int b = binof[i];
        int pos = gbase[b] + (i - segoff[b]);
        if (pos < CAPB)                          // never triggers; OOB guard
            d_edges[b * CAPB + pos] = stage[i];
    }
}

// ---------------- binned degree ----------------

__global__ void k_deg() {
    __shared__ int acc[BINW];
    int tid = threadIdx.x;
    int bin = blockIdx.x / NCHUNK, ch = blockIdx.x % NCHUNK;
    for (int i = tid; i < BINW; i += 256) acc[i] = 0;
    __syncthreads();
    int cnt  = d_cur[bin];
    int base = bin * CAPB;
    int lo = base + (int)((long long)cnt * ch / NCHUNK);
    int hi = base + (int)((long long)cnt * (ch + 1) / NCHUNK);
    for (int e = lo + tid; e < hi; e += 256)
        atomicAdd(&acc[__ldcs(&d_edges[e]) >> 18], 1);
    __syncthreads();
    for (int ld = tid; ld < BINW; ld += 256) {
        int v = acc[ld];
        if (v)
            asm volatile("red.global.add.u32 [%0], %1;"
                         :: "l"(&d_cnt[(bin << BSHIFT) + ld]), "r"(v) : "memory");
    }
}

// ---------------- dense node kernels ----------------

__global__ void k_nodeA(const float2* __restrict__ x) {
    int i = blockIdx.x * blockDim.x + threadIdx.x;
    if (i >= NN) return;
    float deg  = (float)d_cnt[i] + 1.0f;        // +1 self-loop
    float dinv = rsqrtf(deg);
    d_dinv[i] = dinv;
    float2 xv = x[i];
    d_g[i] = make_float2(xv.x * dinv, xv.y * dinv);
}

__global__ void k_nodeB(const float2* __restrict__ x,
                        const float*  __restrict__ W1,   // [2,16]
                        const float*  __restrict__ b1,   // [16]
                        const float*  __restrict__ W2) { // [16,2]
    int i = blockIdx.x * blockDim.x + threadIdx.x;
    if (i >= NN) return;
    float dinv = d_dinv[i];
    float idg  = dinv * dinv;
    float2 xv  = __ldg(&x[i]);
    float2 u   = d_u[i];
    float ax = fmaf(u.x, dinv, xv.x * idg);
    float ay = fmaf(u.y, dinv, xv.y * idg);
    float h20 = 0.f, h21 = 0.f;
#pragma unroll
    for (int f = 0; f < 16; f++) {
        float a = fmaf(ax, __ldg(&W1[f]), fmaf(ay, __ldg(&W1[16 + f]), __ldg(&b1[f])));
        a = fmaxf(a, 0.f);
        h20 = fmaf(a, __ldg(&W2[2 * f]),     h20);
        h21 = fmaf(a, __ldg(&W2[2 * f + 1]), h21);
    }
    d_h2[i] = make_float2(h20, h21);
    d_g[i]  = make_float2(h20 * dinv, h21 * dinv);
    d_u[i]  = make_float2(0.f, 0.f);            // re-zero for pass 2
}

__global__ void k_nodeC(const float* __restrict__ b2, float2* __restrict__ out) {
    int i = blockIdx.x * blockDim.x + threadIdx.x;
    if (i >= NN) return;
    float dinv = d_dinv[i];
    float idg  = dinv * dinv;
    float2 u  = d_u[i];
    float2 h2 = d_h2[i];
    out[i] = make_float2(fmaf(u.x, dinv, fmaf(h2.x, idg, __ldg(&b2[0]))),
                         fmaf(u.y, dinv, fmaf(h2.y, idg, __ldg(&b2[1]))));
}

// ---------------- binned gather + smem-accumulate pass ----------------

__global__ void k_pass() {
    __shared__ float accx[BINW];
    __shared__ float accy[BINW];
    int tid = threadIdx.x;
    int bin = blockIdx.x / NCHUNK, ch = blockIdx.x % NCHUNK;
    for (int i = tid; i < BINW; i += 256) { accx[i] = 0.f; accy[i] = 0.f; }
    __syncthreads();
    int cnt  = d_cur[bin];
    int base = bin * CAPB;
    int lo = base + (int)((long long)cnt * ch / NCHUNK);
    int hi = base + (int)((long long)cnt * (ch + 1) / NCHUNK);
    int e = lo + tid;
    for (; e + 3 * 256 < hi; e += 4 * 256) {
        unsigned w0 = __ldcs(&d_edges[e]);
        unsigned w1 = __ldcs(&d_edges[e + 256]);
        unsigned w2 = __ldcs(&d_edges[e + 512]);
        unsigned w3 = __ldcs(&d_edges[e + 768]);
        float2 g0 = __ldg(&d_g[w0 & 0x3FFFFu]);
        float2 g1 = __ldg(&d_g[w1 & 0x3FFFFu]);
        float2 g2 = __ldg(&d_g[w2 & 0x3FFFFu]);
        float2 g3 = __ldg(&d_g[w3 & 0x3FFFFu]);
        atomicAdd(&accx[w0 >> 18], g0.x); atomicAdd(&accy[w0 >> 18], g0.y);
        atomicAdd(&accx[w1 >> 18], g1.x); atomicAdd(&accy[w1 >> 18], g1.y);
        atomicAdd(&accx[w2 >> 18], g2.x); atomicAdd(&accy[w2 >> 18], g2.y);
        atomicAdd(&accx[w3 >> 18], g3.x); atomicAdd(&accy[w3 >> 18], g3.y);
    }
    for (; e < hi; e += 256) {
        unsigned w = __ldcs(&d_edges[e]);
        float2 g = __ldg(&d_g[w & 0x3FFFFu]);
        atomicAdd(&accx[w >> 18], g.x);
        atomicAdd(&accy[w >> 18], g.y);
    }
    __syncthreads();
    for (int ld = tid; ld < BINW; ld += 256) {
        float vx = accx[ld], vy = accy[ld];
        if (vx != 0.f || vy != 0.f)
            asm volatile("red.global.add.v2.f32 [%0], {%1, %2};"
                         :: "l"(&d_u[(bin << BSHIFT) + ld]), "f"(vx), "f"(vy) : "memory");
    }
}

// ---------------- launch ----------------

extern "C" void kernel_launch(void* const* d_in, const int* in_sizes, int n_in,
                              void* d_out, int out_size) {
    // metadata order: x, W1, b1, W2, b2, edge_index
    const float2* x  = (const float2*)d_in[0];
    const float*  W1 = (const float*) d_in[1];
    const float*  b1 = (const float*) d_in[2];
    const float*  W2 = (const float*) d_in[3];
    const float*  b2 = (const float*) d_in[4];
    const int*    ei = (const int*)   d_in[5];     // [2, NE] row-major
    const int4*   src4 = (const int4*)(ei);
    const int4*   dst4 = (const int4*)(ei + NE);
    float2* out = (float2*)d_out;

    const int NT = 256;
    const int nodeBlocks = (NN + NT - 1) / NT;
    const int HALF = (NPAD + 1) / 2;
    const int hBlocks = (HALF + NT - 1) / NT;
    const int dpBlocks = NBINS * NCHUNK;            // 784

    k_zero_cur<<<1,          128>>>();              // #1
    k_zero_acc<<<hBlocks,    NT>>>(0);              // #2
    k_zero_acc<<<hBlocks,    NT>>>(HALF);           // #3
    k_scatter <<<NTILES,     NT>>>(src4, dst4);     // #4 -> ncu capture slot
    k_deg     <<<dpBlocks,   NT>>>();
    k_nodeA   <<<nodeBlocks, NT>>>(x);
    k_pass    <<<dpBlocks,   NT>>>();
    k_nodeB   <<<nodeBlocks, NT>>>(x, W1, b1, W2);
    k_pass    <<<dpBlocks,   NT>>>();
    k_nodeC   <<<nodeBlocks, NT>>>(b2, out);
}

// round 12
// speedup vs baseline: 1.2393x; 1.0815x over previous
#include <cuda_runtime.h>

// GCN 2-layer, GB300 — round 12: R11 base, pass/deg issue-pressure cuts.
// Measured (R11): scatter 61.7 (near floor), deg 17, passes ~75 each (now
// dominant: 25.6M smem ATOMS + 12.8M gather wavefronts + scalar reads).
// R12: uint4 edge reads (4x fewer load instrs), NCHUNK 8->6 (3.97 waves,
// kills the 30%-empty tail wave), d_cnt zero folded into scatter.
// Launch #4 = k_deg (the ncu capture slot) to probe the read/ATOMS mix.

#define NN     200000
#define NE     12800000
#define BSHIFT 11
#define BINW   2048
#define NBINS  98                    // ceil(NN / BINW)
#define NPAD   (NBINS * BINW)        // 200704
#define TILE   2048
#define NTILES (NE / TILE)           // 6250
#define CAPB   140000                // per-bin capacity; CAPB%4==0
#define CAPB4  (CAPB / 4)
#define NCHUNK 6                     // 98*6=588 blocks = 3.97 waves of 148

__device__ unsigned d_edges[NBINS * CAPB];  // packed (localdst<<18)|src
__device__ int      d_cur[NBINS];           // per-bin write cursors
__device__ int      d_cnt[NPAD];
__device__ float2   d_u  [NPAD];
__device__ float    d_dinv[NN];
__device__ float2   d_g  [NN];
__device__ float2   d_h2 [NN];

// ---------------- init ----------------

__global__ void k_zero_cur() {
    int i = threadIdx.x;
    if (i < NBINS) d_cur[i] = 0;
}

__global__ void k_zero_u() {
    int i = blockIdx.x * blockDim.x + threadIdx.x;
    if (i < NPAD) d_u[i] = make_float2(0.f, 0.f);
}

// ---------------- partition: tile-staged, coalesced writes ----------------

__global__ void k_scatter(const int4* __restrict__ src4,
                          const int4* __restrict__ dst4) {
    __shared__ unsigned stage[TILE];             // 8 KB
    __shared__ unsigned char binof[TILE];        // 2 KB
    __shared__ int cnt[2][NBINS];                // replicated rank counters
    __shared__ int segoff[NBINS];
    __shared__ int base1[NBINS];
    __shared__ int gbase[NBINS];
    __shared__ int total[NBINS];
    int tid = threadIdx.x;
    int rep = (tid >> 5) & 1;
    // folded: zero d_cnt (consumed only by k_deg, a later kernel)
    {
        int i = blockIdx.x * 256 + tid;
        if (i < NPAD) d_cnt[i] = 0;
    }
    for (int i = tid; i < 2 * NBINS; i += 256) ((int*)cnt)[i] = 0;
    int b4 = blockIdx.x * (TILE / 4);
    int4 sa = __ldcs(&src4[b4 + tid]);
    int4 sb = __ldcs(&src4[b4 + 256 + tid]);
    int4 da = __ldcs(&dst4[b4 + tid]);
    int4 db = __ldcs(&dst4[b4 + 256 + tid]);
    int ss[8] = {sa.x, sa.y, sa.z, sa.w, sb.x, sb.y, sb.z, sb.w};
    int dd[8] = {da.x, da.y, da.z, da.w, db.x, db.y, db.z, db.w};
    __syncthreads();
    unsigned wd[8]; int bn[8], rk[8];
#pragma unroll
    for (int r = 0; r < 8; r++) {
        bn[r] = dd[r] >> BSHIFT;
        wd[r] = ((unsigned)(dd[r] & (BINW - 1)) << 18) | (unsigned)ss[r];
        rk[r] = atomicAdd(&cnt[rep][bn[r]], 1);
    }
    __syncthreads();
    if (tid == 0) {                              // 98-entry serial scan
        int run = 0;
#pragma unroll 1
        for (int b = 0; b < NBINS; b++) {
            int c0 = cnt[0][b], c1 = cnt[1][b];
            segoff[b] = run;
            base1[b]  = run + c0;
            total[b]  = c0 + c1;
            run += c0 + c1;
        }
    }
    __syncthreads();
    if (tid < NBINS) gbase[tid] = atomicAdd(&d_cur[tid], total[tid]);
#pragma unroll
    for (int r = 0; r < 8; r++) {
        int p = (rep ? base1[bn[r]] : segoff[bn[r]]) + rk[r];
        stage[p] = wd[r];
        binof[p] = (unsigned char)bn[r];
    }
    __syncthreads();
    for (int i = tid; i < TILE; i += 256) {
        int b = binof[i];
        int pos = gbase[b] + (i - segoff[b]);
        if (pos < CAPB)                          // never triggers; OOB guard
            d_edges[b * CAPB + pos] = stage[i];
    }
}

// ---------------- chunk bounds (quad-aligned) ----------------

__device__ __forceinline__ void chunk_quads(int cnt, int ch,
                                            int& q_lo, int& q_hi, int& tail_lo, int& tail_hi) {
    long long lo = ((long long)cnt * ch / NCHUNK) & ~3LL;
    long long hi = (ch == NCHUNK - 1) ? (long long)cnt
                                      : (((long long)cnt * (ch + 1) / NCHUNK) & ~3LL);
    q_lo = (int)(lo >> 2);
    q_hi = (int)(hi >> 2);            // full quads
    tail_lo = (ch == NCHUNK - 1) ? (cnt & ~3) : 0;
    tail_hi = (ch == NCHUNK - 1) ? cnt : 0;
}

// ---------------- binned degree (uint4 reads) ----------------

__global__ void k_deg() {
    __shared__ int acc[BINW];
    int tid = threadIdx.x;
    int bin = blockIdx.x / NCHUNK, ch = blockIdx.x % NCHUNK;
    for (int i = tid; i < BINW; i += 256) acc[i] = 0;
    __syncthreads();
    int cnt = d_cur[bin];
    int q_lo, q_hi, t_lo, t_hi;
    chunk_quads(cnt, ch, q_lo, q_hi, t_lo, t_hi);
    const uint4* E4 = (const uint4*)d_edges;
    int b4 = bin * CAPB4;
    for (int q = q_lo + tid; q < q_hi; q += 256) {
        uint4 w = __ldcs(&E4[b4 + q]);
        atomicAdd(&acc[w.x >> 18], 1);
        atomicAdd(&acc[w.y >> 18], 1);
        atomicAdd(&acc[w.z >> 18], 1);
        atomicAdd(&acc[w.w >> 18], 1);
    }
    for (int e = t_lo + tid; e < t_hi; e += 256)
        atomicAdd(&acc[__ldcs(&d_edges[bin * CAPB + e]) >> 18], 1);
    __syncthreads();
    for (int ld = tid; ld < BINW; ld += 256) {
        int v = acc[ld];
        if (v)
            asm volatile("red.global.add.u32 [%0], %1;"
                         :: "l"(&d_cnt[(bin << BSHIFT) + ld]), "r"(v) : "memory");
    }
}

// ---------------- dense node kernels ----------------

__global__ void k_nodeA(const float2* __restrict__ x) {
    int i = blockIdx.x * blockDim.x + threadIdx.x;
    if (i >= NN) return;
    float deg  = (float)d_cnt[i] + 1.0f;        // +1 self-loop
    float dinv = rsqrtf(deg);
    d_dinv[i] = dinv;
    float2 xv = x[i];
    d_g[i] = make_float2(xv.x * dinv, xv.y * dinv);
}

__global__ void k_nodeB(const float2* __restrict__ x,
                        const float*  __restrict__ W1,   // [2,16]
                        const float*  __restrict__ b1,   // [16]
                        const float*  __restrict__ W2) { // [16,2]
    int i = blockIdx.x * blockDim.x + threadIdx.x;
    if (i >= NN) return;
    float dinv = d_dinv[i];
    float idg  = dinv * dinv;
    float2 xv  = __ldg(&x[i]);
    float2 u   = d_u[i];
    float ax = fmaf(u.x, dinv, xv.x * idg);
    float ay = fmaf(u.y, dinv, xv.y * idg);
    float h20 = 0.f, h21 = 0.f;
#pragma unroll
    for (int f = 0; f < 16; f++) {
        float a = fmaf(ax, __ldg(&W1[f]), fmaf(ay, __ldg(&W1[16 + f]), __ldg(&b1[f])));
        a = fmaxf(a, 0.f);
        h20 = fmaf(a, __ldg(&W2[2 * f]),     h20);
        h21 = fmaf(a, __ldg(&W2[2 * f + 1]), h21);
    }
    d_h2[i] = make_float2(h20, h21);
    d_g[i]  = make_float2(h20 * dinv, h21 * dinv);
    d_u[i]  = make_float2(0.f, 0.f);            // re-zero for pass 2
}

__global__ void k_nodeC(const float* __restrict__ b2, float2* __restrict__ out) {
    int i = blockIdx.x * blockDim.x + threadIdx.x;
    if (i >= NN) return;
    float dinv = d_dinv[i];
    float idg  = dinv * dinv;
    float2 u  = d_u[i];
    float2 h2 = d_h2[i];
    out[i] = make_float2(fmaf(u.x, dinv, fmaf(h2.x, idg, __ldg(&b2[0]))),
                         fmaf(u.y, dinv, fmaf(h2.y, idg, __ldg(&b2[1]))));
}

// ---------------- binned gather pass (uint4 reads) ----------------

__global__ void k_pass() {
    __shared__ float accx[BINW];
    __shared__ float accy[BINW];
    int tid = threadIdx.x;
    int bin = blockIdx.x / NCHUNK, ch = blockIdx.x % NCHUNK;
    for (int i = tid; i < BINW; i += 256) { accx[i] = 0.f; accy[i] = 0.f; }
    __syncthreads();
    int cnt = d_cur[bin];
    int q_lo, q_hi, t_lo, t_hi;
    chunk_quads(cnt, ch, q_lo, q_hi, t_lo, t_hi);
    const uint4* E4 = (const uint4*)d_edges;
    int b4 = bin * CAPB4;
    for (int q = q_lo + tid; q < q_hi; q += 256) {
        uint4 w = __ldcs(&E4[b4 + q]);
        float2 g0 = __ldg(&d_g[w.x & 0x3FFFFu]);
        float2 g1 = __ldg(&d_g[w.y & 0x3FFFFu]);
        float2 g2 = __ldg(&d_g[w.z & 0x3FFFFu]);
        float2 g3 = __ldg(&d_g[w.w & 0x3FFFFu]);
        atomicAdd(&accx[w.x >> 18], g0.x); atomicAdd(&accy[w.x >> 18], g0.y);
        atomicAdd(&accx[w.y >> 18], g1.x); atomicAdd(&accy[w.y >> 18], g1.y);
        atomicAdd(&accx[w.z >> 18], g2.x); atomicAdd(&accy[w.z >> 18], g2.y);
        atomicAdd(&accx[w.w >> 18], g3.x); atomicAdd(&accy[w.w >> 18], g3.y);
    }
    for (int e = t_lo + tid; e < t_hi; e += 256) {
        unsigned w = __ldcs(&d_edges[bin * CAPB + e]);
        float2 g = __ldg(&d_g[w & 0x3FFFFu]);
        atomicAdd(&accx[w >> 18], g.x);
        atomicAdd(&accy[w >> 18], g.y);
    }
    __syncthreads();
    for (int ld = tid; ld < BINW; ld += 256) {
        float vx = accx[ld], vy = accy[ld];
        if (vx != 0.f || vy != 0.f)
            asm volatile("red.global.add.v2.f32 [%0], {%1, %2};"
                         :: "l"(&d_u[(bin << BSHIFT) + ld]), "f"(vx), "f"(vy) : "memory");
    }
}

// ---------------- launch ----------------

extern "C" void kernel_launch(void* const* d_in, const int* in_sizes, int n_in,
                              void* d_out, int out_size) {
    // metadata order: x, W1, b1, W2, b2, edge_index
    const float2* x  = (const float2*)d_in[0];
    const float*  W1 = (const float*) d_in[1];
    const float*  b1 = (const float*) d_in[2];
    const float*  W2 = (const float*) d_in[3];
    const float*  b2 = (const float*) d_in[4];
    const int*    ei = (const int*)   d_in[5];     // [2, NE] row-major
    const int4*   src4 = (const int4*)(ei);
    const int4*   dst4 = (const int4*)(ei + NE);
    float2* out = (float2*)d_out;

    const int NT = 256;
    const int nodeBlocks = (NN + NT - 1) / NT;
    const int padBlocks  = (NPAD + NT - 1) / NT;
    const int dpBlocks   = NBINS * NCHUNK;          // 588

    k_zero_cur<<<1,          128>>>();              // #1
    k_scatter <<<NTILES,     NT>>>(src4, dst4);     // #2 (folds d_cnt zero)
    k_zero_u  <<<padBlocks,  NT>>>();               // #3
    k_deg     <<<dpBlocks,   NT>>>();               // #4 -> ncu capture slot
    k_nodeA   <<<nodeBlocks, NT>>>(x);
    k_pass    <<<dpBlocks,   NT>>>();
    k_nodeB   <<<nodeBlocks, NT>>>(x, W1, b1, W2);
    k_pass    <<<dpBlocks,   NT>>>();
    k_nodeC   <<<nodeBlocks, NT>>>(b2, out);
}